// round 9
// baseline (speedup 1.0000x reference)
#include <cuda_runtime.h>
#include <cuda_bf16.h>

// TD loss backward recurrence, T=256, B=65536.
// R9: width extrapolation test. LDG.32 -> 39-62% DRAM, LDG.64 -> ~82%
// (plateau across BATCH/regs/block-size). M_max ~55 *requests* per warp is
// width-independent, so LDG.128 doubles the per-warp in-flight byte ceiling:
// float4/int4, 4 cols/thread, BATCH=2 double-buffered = 28 LDG.128 = 14 KB
// in flight/warp, 512 single-warp blocks.

#define TD_T 256
#define TD_GAMMA 0.99f
#define BATCH 2
#define NBATCH 127   // batches cover t = 253 .. 0 (t=254 peeled)

struct Buf {
    float4 d[BATCH], r[BATCH], tv[BATCH], vl[BATCH];
    int4   st[BATCH], rb[BATCH], tn[BATCH];
};

__device__ __forceinline__ void load_batch(
    Buf& bf, int j, int q, int Q,
    const float4* __restrict__ rw4, const float4* __restrict__ dc4,
    const float4* __restrict__ vl4, const float4* __restrict__ tv4,
    const int4* __restrict__ st4, const int4* __restrict__ rb4,
    const int4* __restrict__ tb4)
{
    const int tb_hi = 253 - BATCH * j;   // 253, 251, ..., 1
    #pragma unroll
    for (int k = 0; k < BATCH; ++k) {
        const int t  = tb_hi - k;
        const int i  = t * Q + q;
        const int i1 = i + Q;
        bf.d[k]  = __ldcs(&dc4[i1]);
        bf.r[k]  = __ldcs(&rw4[i1]);
        bf.st[k] = __ldcs(&st4[i]);
        bf.rb[k] = __ldcs(&rb4[i]);
        bf.tn[k] = __ldcs(&tb4[i]);
        bf.tv[k] = __ldcs(&tv4[i]);
        bf.vl[k] = __ldcs(&vl4[i]);
    }
}

__device__ __forceinline__ void step_lane(
    float& acc, int st, int rb, int tn, float d, float r, float tv, float vl,
    bool nz, float& o)
{
    const bool l = (st == 2) || (nz && ((rb | tn) != 0));
    const float ret = fmaf(acc, d * TD_GAMMA, r);
    acc = l ? tv : ret;
    const float diff = ret - vl;
    o = diff * diff;
}

__device__ __forceinline__ void compute_batch(
    const Buf& bf, int j, int q, int Q, float4& acc,
    float4* __restrict__ ot4)
{
    const int tb_hi = 253 - BATCH * j;
    #pragma unroll
    for (int k = 0; k < BATCH; ++k) {
        const int t = tb_hi - k;
        const bool nz = (t != 0);
        float4 o;
        step_lane(acc.x, bf.st[k].x, bf.rb[k].x, bf.tn[k].x,
                  bf.d[k].x, bf.r[k].x, bf.tv[k].x, bf.vl[k].x, nz, o.x);
        step_lane(acc.y, bf.st[k].y, bf.rb[k].y, bf.tn[k].y,
                  bf.d[k].y, bf.r[k].y, bf.tv[k].y, bf.vl[k].y, nz, o.y);
        step_lane(acc.z, bf.st[k].z, bf.rb[k].z, bf.tn[k].z,
                  bf.d[k].z, bf.r[k].z, bf.tv[k].z, bf.vl[k].z, nz, o.z);
        step_lane(acc.w, bf.st[k].w, bf.rb[k].w, bf.tn[k].w,
                  bf.d[k].w, bf.r[k].w, bf.tv[k].w, bf.vl[k].w, nz, o.w);
        __stcs(&ot4[t * Q + q], o);
    }
}

__global__ void __launch_bounds__(32, 1) td_loss_kernel(
    const float* __restrict__ reward,
    const float* __restrict__ discount,
    const float* __restrict__ value,
    const float* __restrict__ target_value,
    const int*   __restrict__ step_type,
    const int*   __restrict__ rollout_b,
    const int*   __restrict__ train_b,
    float*       __restrict__ out,
    int B)
{
    const int q = blockIdx.x * blockDim.x + threadIdx.x;  // quad index
    const int Q = B >> 2;
    if (q >= Q) return;

    const float4* __restrict__ rw4 = (const float4*)reward;
    const float4* __restrict__ dc4 = (const float4*)discount;
    const float4* __restrict__ vl4 = (const float4*)value;
    const float4* __restrict__ tv4 = (const float4*)target_value;
    const int4*   __restrict__ st4 = (const int4*)step_type;
    const int4*   __restrict__ rb4 = (const int4*)rollout_b;
    const int4*   __restrict__ tb4 = (const int4*)train_b;
    float4*       __restrict__ ot4 = (float4*)out;

    const int base = (TD_T - 1) * Q + q;
    float4 acc = __ldcs(&tv4[base]);
    __stcs(&ot4[base], make_float4(0.0f, 0.0f, 0.0f, 0.0f));

    // Peel t = 254 (t > 0).
    {
        const int t  = TD_T - 2;
        const int i  = t * Q + q;
        const int i1 = i + Q;
        const float4 d  = __ldcs(&dc4[i1]);
        const float4 r  = __ldcs(&rw4[i1]);
        const int4   st = __ldcs(&st4[i]);
        const int4   rb = __ldcs(&rb4[i]);
        const int4   tn = __ldcs(&tb4[i]);
        const float4 tv = __ldcs(&tv4[i]);
        const float4 vl = __ldcs(&vl4[i]);
        float4 o;
        step_lane(acc.x, st.x, rb.x, tn.x, d.x, r.x, tv.x, vl.x, true, o.x);
        step_lane(acc.y, st.y, rb.y, tn.y, d.y, r.y, tv.y, vl.y, true, o.y);
        step_lane(acc.z, st.z, rb.z, tn.z, d.z, r.z, tv.z, vl.z, true, o.z);
        step_lane(acc.w, st.w, rb.w, tn.w, d.w, r.w, tv.w, vl.w, true, o.w);
        __stcs(&ot4[i], o);
    }

    // Double-buffered pipeline over 127 batches (odd): unroll by 2 + epilogue.
    Buf bufA, bufB;
    load_batch(bufA, 0, q, Q, rw4, dc4, vl4, tv4, st4, rb4, tb4);

    #pragma unroll 1
    for (int j = 0; j + 1 < NBATCH; j += 2) {
        load_batch(bufB, j + 1, q, Q, rw4, dc4, vl4, tv4, st4, rb4, tb4);
        compute_batch(bufA, j, q, Q, acc, ot4);
        if (j + 2 < NBATCH)
            load_batch(bufA, j + 2, q, Q, rw4, dc4, vl4, tv4, st4, rb4, tb4);
        compute_batch(bufB, j + 1, q, Q, acc, ot4);
    }
    // Final batch (j = 126) already resident in bufA.
    compute_batch(bufA, NBATCH - 1, q, Q, acc, ot4);
}

extern "C" void kernel_launch(void* const* d_in, const int* in_sizes, int n_in,
                              void* d_out, int out_size)
{
    const float* reward       = (const float*)d_in[0];
    const float* discount     = (const float*)d_in[1];
    const float* value        = (const float*)d_in[2];
    const float* target_value = (const float*)d_in[3];
    const int*   step_type    = (const int*)d_in[4];
    const int*   rollout_b    = (const int*)d_in[5];
    const int*   train_b      = (const int*)d_in[6];
    float*       out          = (float*)d_out;

    const int B = in_sizes[0] / TD_T;
    const int quads = B / 4;

    const int threads = 32;
    const int blocks  = (quads + threads - 1) / threads;
    td_loss_kernel<<<blocks, threads>>>(reward, discount, value, target_value,
                                        step_type, rollout_b, train_b, out, B);
}

// round 10
// speedup vs baseline: 1.1362x; 1.1362x over previous
#include <cuda_runtime.h>
#include <cuda_bf16.h>

// TD loss backward recurrence, T=256, B=65536. FINAL (= R4, empirical argmax).
// Design-space conclusion after 9 rounds: LDG.64 (float2) + double-buffered
// 4-step batches + 64-thread blocks sits on the ~82%-DRAM plateau (6.5 TB/s
// effective on a 7-read/1-write mixed stream). Scalar loads (39-62% DRAM),
// float4 (72.6%, too few warps), triple buffering (254-reg wall), BATCH 3/5,
// and 32-thread blocks were all neutral or worse.

#define TD_T 256
#define TD_GAMMA 0.99f
#define BATCH 4
#define NBATCH 63   // batches cover t = 251 .. 0

struct Buf {
    float2 d[BATCH], r[BATCH], tv[BATCH], vl[BATCH];
    int2   st[BATCH], rb[BATCH], tn[BATCH];
};

__device__ __forceinline__ void load_batch(
    Buf& bf, int j, int p, int P,
    const float2* __restrict__ rw2, const float2* __restrict__ dc2,
    const float2* __restrict__ vl2, const float2* __restrict__ tv2,
    const int2* __restrict__ st2, const int2* __restrict__ rb2,
    const int2* __restrict__ tb2)
{
    const int tb_hi = 251 - 4 * j;
    #pragma unroll
    for (int k = 0; k < BATCH; ++k) {
        const int t  = tb_hi - k;
        const int i  = t * P + p;
        const int i1 = i + P;
        bf.d[k]  = __ldcs(&dc2[i1]);
        bf.r[k]  = __ldcs(&rw2[i1]);
        bf.st[k] = __ldcs(&st2[i]);
        bf.rb[k] = __ldcs(&rb2[i]);
        bf.tn[k] = __ldcs(&tb2[i]);
        bf.tv[k] = __ldcs(&tv2[i]);
        bf.vl[k] = __ldcs(&vl2[i]);
    }
}

__device__ __forceinline__ void compute_batch(
    const Buf& bf, int j, int p, int P, float2& acc,
    float2* __restrict__ ot2)
{
    const int tb_hi = 251 - 4 * j;
    #pragma unroll
    for (int k = 0; k < BATCH; ++k) {
        const int t = tb_hi - k;
        const bool nz = (t != 0);
        const bool lx = (bf.st[k].x == 2) || (nz && ((bf.rb[k].x | bf.tn[k].x) != 0));
        const bool ly = (bf.st[k].y == 2) || (nz && ((bf.rb[k].y | bf.tn[k].y) != 0));
        const float retx = fmaf(acc.x, bf.d[k].x * TD_GAMMA, bf.r[k].x);
        const float rety = fmaf(acc.y, bf.d[k].y * TD_GAMMA, bf.r[k].y);
        acc.x = lx ? bf.tv[k].x : retx;
        acc.y = ly ? bf.tv[k].y : rety;
        const float dx = retx - bf.vl[k].x;
        const float dy = rety - bf.vl[k].y;
        __stcs(&ot2[t * P + p], make_float2(dx * dx, dy * dy));
    }
}

__global__ void __launch_bounds__(64, 1) td_loss_kernel(
    const float* __restrict__ reward,
    const float* __restrict__ discount,
    const float* __restrict__ value,
    const float* __restrict__ target_value,
    const int*   __restrict__ step_type,
    const int*   __restrict__ rollout_b,
    const int*   __restrict__ train_b,
    float*       __restrict__ out,
    int B)
{
    const int p = blockIdx.x * blockDim.x + threadIdx.x;
    const int P = B >> 1;
    if (p >= P) return;

    const float2* __restrict__ rw2 = (const float2*)reward;
    const float2* __restrict__ dc2 = (const float2*)discount;
    const float2* __restrict__ vl2 = (const float2*)value;
    const float2* __restrict__ tv2 = (const float2*)target_value;
    const int2*   __restrict__ st2 = (const int2*)step_type;
    const int2*   __restrict__ rb2 = (const int2*)rollout_b;
    const int2*   __restrict__ tb2 = (const int2*)train_b;
    float2*       __restrict__ ot2 = (float2*)out;

    const int base = (TD_T - 1) * P + p;
    float2 acc = __ldcs(&tv2[base]);
    __stcs(&ot2[base], make_float2(0.0f, 0.0f));

    // Peel t = 254, 253, 252 (all t > 0 here).
    #pragma unroll
    for (int t = TD_T - 2; t >= 252; --t) {
        const int i  = t * P + p;
        const int i1 = i + P;
        const float2 d  = __ldcs(&dc2[i1]);
        const float2 r  = __ldcs(&rw2[i1]);
        const int2   st = __ldcs(&st2[i]);
        const int2   rb = __ldcs(&rb2[i]);
        const int2   tn = __ldcs(&tb2[i]);
        const float2 tv = __ldcs(&tv2[i]);
        const float2 vl = __ldcs(&vl2[i]);
        const bool lx = (st.x == 2) || ((rb.x | tn.x) != 0);
        const bool ly = (st.y == 2) || ((rb.y | tn.y) != 0);
        const float retx = fmaf(acc.x, d.x * TD_GAMMA, r.x);
        const float rety = fmaf(acc.y, d.y * TD_GAMMA, r.y);
        acc.x = lx ? tv.x : retx;
        acc.y = ly ? tv.y : rety;
        const float dx = retx - vl.x;
        const float dy = rety - vl.y;
        __stcs(&ot2[i], make_float2(dx * dx, dy * dy));
    }

    // Pipelined main loop: 63 batches (odd), unrolled by 2 with an epilogue.
    Buf bufA, bufB;
    load_batch(bufA, 0, p, P, rw2, dc2, vl2, tv2, st2, rb2, tb2);

    #pragma unroll 1
    for (int j = 0; j + 1 < NBATCH; j += 2) {
        load_batch(bufB, j + 1, p, P, rw2, dc2, vl2, tv2, st2, rb2, tb2);
        compute_batch(bufA, j, p, P, acc, ot2);
        if (j + 2 < NBATCH)
            load_batch(bufA, j + 2, p, P, rw2, dc2, vl2, tv2, st2, rb2, tb2);
        compute_batch(bufB, j + 1, p, P, acc, ot2);
    }
    // j == 62: final batch already resident in bufA.
    compute_batch(bufA, NBATCH - 1, p, P, acc, ot2);
}

extern "C" void kernel_launch(void* const* d_in, const int* in_sizes, int n_in,
                              void* d_out, int out_size)
{
    const float* reward       = (const float*)d_in[0];
    const float* discount     = (const float*)d_in[1];
    const float* value        = (const float*)d_in[2];
    const float* target_value = (const float*)d_in[3];
    const int*   step_type    = (const int*)d_in[4];
    const int*   rollout_b    = (const int*)d_in[5];
    const int*   train_b      = (const int*)d_in[6];
    float*       out          = (float*)d_out;

    const int B = in_sizes[0] / TD_T;
    const int pairs = B / 2;

    const int threads = 64;
    const int blocks  = (pairs + threads - 1) / threads;
    td_loss_kernel<<<blocks, threads>>>(reward, discount, value, target_value,
                                        step_type, rollout_b, train_b, out, B);
}

// round 11
// speedup vs baseline: 1.1561x; 1.0175x over previous
#include <cuda_runtime.h>
#include <cuda_bf16.h>

// TD loss backward recurrence, T=256, B=65536. R11 = R4 structure with the
// one never-isolated variable flipped: default (L2-cached) loads instead of
// __ldcs, keeping __stcs on stores. Adjacent warps touch the same 128B line;
// evict-first loads may cost that reuse. Everything else is the proven
// argmax: float2, BATCH=4 double-buffered, 64-thread blocks, 160 regs,
// ~95% of the ~6300 B/cyc LTS structural cap.

#define TD_T 256
#define TD_GAMMA 0.99f
#define BATCH 4
#define NBATCH 63   // batches cover t = 251 .. 0

struct Buf {
    float2 d[BATCH], r[BATCH], tv[BATCH], vl[BATCH];
    int2   st[BATCH], rb[BATCH], tn[BATCH];
};

__device__ __forceinline__ void load_batch(
    Buf& bf, int j, int p, int P,
    const float2* __restrict__ rw2, const float2* __restrict__ dc2,
    const float2* __restrict__ vl2, const float2* __restrict__ tv2,
    const int2* __restrict__ st2, const int2* __restrict__ rb2,
    const int2* __restrict__ tb2)
{
    const int tb_hi = 251 - 4 * j;
    #pragma unroll
    for (int k = 0; k < BATCH; ++k) {
        const int t  = tb_hi - k;
        const int i  = t * P + p;
        const int i1 = i + P;
        bf.d[k]  = dc2[i1];
        bf.r[k]  = rw2[i1];
        bf.st[k] = st2[i];
        bf.rb[k] = rb2[i];
        bf.tn[k] = tb2[i];
        bf.tv[k] = tv2[i];
        bf.vl[k] = vl2[i];
    }
}

__device__ __forceinline__ void compute_batch(
    const Buf& bf, int j, int p, int P, float2& acc,
    float2* __restrict__ ot2)
{
    const int tb_hi = 251 - 4 * j;
    #pragma unroll
    for (int k = 0; k < BATCH; ++k) {
        const int t = tb_hi - k;
        const bool nz = (t != 0);
        const bool lx = (bf.st[k].x == 2) || (nz && ((bf.rb[k].x | bf.tn[k].x) != 0));
        const bool ly = (bf.st[k].y == 2) || (nz && ((bf.rb[k].y | bf.tn[k].y) != 0));
        const float retx = fmaf(acc.x, bf.d[k].x * TD_GAMMA, bf.r[k].x);
        const float rety = fmaf(acc.y, bf.d[k].y * TD_GAMMA, bf.r[k].y);
        acc.x = lx ? bf.tv[k].x : retx;
        acc.y = ly ? bf.tv[k].y : rety;
        const float dx = retx - bf.vl[k].x;
        const float dy = rety - bf.vl[k].y;
        __stcs(&ot2[t * P + p], make_float2(dx * dx, dy * dy));
    }
}

__global__ void __launch_bounds__(64, 1) td_loss_kernel(
    const float* __restrict__ reward,
    const float* __restrict__ discount,
    const float* __restrict__ value,
    const float* __restrict__ target_value,
    const int*   __restrict__ step_type,
    const int*   __restrict__ rollout_b,
    const int*   __restrict__ train_b,
    float*       __restrict__ out,
    int B)
{
    const int p = blockIdx.x * blockDim.x + threadIdx.x;
    const int P = B >> 1;
    if (p >= P) return;

    const float2* __restrict__ rw2 = (const float2*)reward;
    const float2* __restrict__ dc2 = (const float2*)discount;
    const float2* __restrict__ vl2 = (const float2*)value;
    const float2* __restrict__ tv2 = (const float2*)target_value;
    const int2*   __restrict__ st2 = (const int2*)step_type;
    const int2*   __restrict__ rb2 = (const int2*)rollout_b;
    const int2*   __restrict__ tb2 = (const int2*)train_b;
    float2*       __restrict__ ot2 = (float2*)out;

    const int base = (TD_T - 1) * P + p;
    float2 acc = tv2[base];
    __stcs(&ot2[base], make_float2(0.0f, 0.0f));

    // Peel t = 254, 253, 252 (all t > 0 here).
    #pragma unroll
    for (int t = TD_T - 2; t >= 252; --t) {
        const int i  = t * P + p;
        const int i1 = i + P;
        const float2 d  = dc2[i1];
        const float2 r  = rw2[i1];
        const int2   st = st2[i];
        const int2   rb = rb2[i];
        const int2   tn = tb2[i];
        const float2 tv = tv2[i];
        const float2 vl = vl2[i];
        const bool lx = (st.x == 2) || ((rb.x | tn.x) != 0);
        const bool ly = (st.y == 2) || ((rb.y | tn.y) != 0);
        const float retx = fmaf(acc.x, d.x * TD_GAMMA, r.x);
        const float rety = fmaf(acc.y, d.y * TD_GAMMA, r.y);
        acc.x = lx ? tv.x : retx;
        acc.y = ly ? tv.y : rety;
        const float dx = retx - vl.x;
        const float dy = rety - vl.y;
        __stcs(&ot2[i], make_float2(dx * dx, dy * dy));
    }

    // Pipelined main loop: 63 batches (odd), unrolled by 2 with an epilogue.
    Buf bufA, bufB;
    load_batch(bufA, 0, p, P, rw2, dc2, vl2, tv2, st2, rb2, tb2);

    #pragma unroll 1
    for (int j = 0; j + 1 < NBATCH; j += 2) {
        load_batch(bufB, j + 1, p, P, rw2, dc2, vl2, tv2, st2, rb2, tb2);
        compute_batch(bufA, j, p, P, acc, ot2);
        if (j + 2 < NBATCH)
            load_batch(bufA, j + 2, p, P, rw2, dc2, vl2, tv2, st2, rb2, tb2);
        compute_batch(bufB, j + 1, p, P, acc, ot2);
    }
    // j == 62: final batch already resident in bufA.
    compute_batch(bufA, NBATCH - 1, p, P, acc, ot2);
}

extern "C" void kernel_launch(void* const* d_in, const int* in_sizes, int n_in,
                              void* d_out, int out_size)
{
    const float* reward       = (const float*)d_in[0];
    const float* discount     = (const float*)d_in[1];
    const float* value        = (const float*)d_in[2];
    const float* target_value = (const float*)d_in[3];
    const int*   step_type    = (const int*)d_in[4];
    const int*   rollout_b    = (const int*)d_in[5];
    const int*   train_b      = (const int*)d_in[6];
    float*       out          = (float*)d_out;

    const int B = in_sizes[0] / TD_T;
    const int pairs = B / 2;

    const int threads = 64;
    const int blocks  = (pairs + threads - 1) / threads;
    td_loss_kernel<<<blocks, threads>>>(reward, discount, value, target_value,
                                        step_type, rollout_b, train_b, out, B);
}